// round 11
// baseline (speedup 1.0000x reference)
#include <cuda_runtime.h>
#include <cuda_bf16.h>

// ---------------- problem constants ----------------
#define BB   2048          // batch / num nodes
#define TT   64            // seq len
#define EE   300           // embed dim = hidden
#define HH   300
#define G4   1200          // 4*H
#define D2   600           // 2*H
#define CC   1024          // num classes
#define NEDGE 65536
#define BT   (BB*TT)       // 131072
#define KCOS (TT*D2)       // 38400
#define KP   152           // k-pairs for H=300 padded to 304
#define HPAD 304           // padded hidden (floats per h row)
#define NPAD 1280          // padded interleaved gate width (10 x 128 tiles)

// ---------------- scratch (device globals; no cudaMalloc allowed) ----------------
__device__ float g_gi [(size_t)2 * BT * NPAD];      // interleaved gate pre-activations (input part)
__device__ float g_c  [(size_t)BT * D2];
__device__ float g_cs [(size_t)2 * BB * HH];
__device__ float g_hf [(size_t)2 * 2 * BB * HPAD];  // DOUBLE-BUFFERED h state [buf][dir][B][HPAD]
__device__ float g_lnn[(size_t)CC * D2];
__device__ float g_hn [(size_t)BB * CC];
__device__ float g_m  [(size_t)BB * CC];
__device__ float g_agg[(size_t)BB * CC];
__device__ float g_gru[(size_t)2 * BB * 3072];
__device__ float g_bsum[(size_t)2 * NPAD];          // bih+bhh, interleaved
// pre-split bf16x2 hi/lo Whh, interleaved rows: [dir][v][kpair]
__device__ unsigned g_whhH[(size_t)2 * NPAD * KP];
__device__ unsigned g_whhL[(size_t)2 * NPAD * KP];

// ---------------- helpers ----------------
__device__ __forceinline__ float sigf(float x) { return 1.0f / (1.0f + __expf(-x)); }
__device__ __forceinline__ float tanhfast(float x) {
    return 2.0f / (1.0f + __expf(-2.0f * x)) - 1.0f;
}

__global__ void zerok(float* __restrict__ p, int n) {
    int i = blockIdx.x * blockDim.x + threadIdx.x;
    if (i < n) p[i] = 0.0f;
}

// ---------------- bf16 split helpers ----------------
__device__ __forceinline__ unsigned pack_hilo(float x, float y, unsigned& lo) {
    __nv_bfloat16 hx = __float2bfloat16_rn(x);
    __nv_bfloat16 hy = __float2bfloat16_rn(y);
    __nv_bfloat16 lx = __float2bfloat16_rn(x - __bfloat162float(hx));
    __nv_bfloat16 ly = __float2bfloat16_rn(y - __bfloat162float(hy));
    __nv_bfloat162 h2 = __halves2bfloat162(hx, hy);
    __nv_bfloat162 l2 = __halves2bfloat162(lx, ly);
    lo = *reinterpret_cast<unsigned*>(&l2);
    return *reinterpret_cast<unsigned*>(&h2);
}

__device__ __forceinline__ void mma_bf16(float* d, const unsigned* a, const unsigned* b) {
    asm volatile(
        "mma.sync.aligned.m16n8k16.row.col.f32.bf16.bf16.f32 "
        "{%0,%1,%2,%3},{%4,%5,%6,%7},{%8,%9},{%0,%1,%2,%3};\n"
        : "+f"(d[0]), "+f"(d[1]), "+f"(d[2]), "+f"(d[3])
        : "r"(a[0]), "r"(a[1]), "r"(a[2]), "r"(a[3]),
          "r"(b[0]), "r"(b[1]));
}

// ---------------- pre-split Whh (interleaved gate rows) ----------------
__global__ void split_whh(const float* __restrict__ Wf, const float* __restrict__ Wb) {
    int i = blockIdx.x * blockDim.x + threadIdx.x;
    if (i >= 2 * NPAD * KP) return;
    int dir = i / (NPAD * KP);
    int rem = i - dir * (NPAD * KP);
    int v  = rem / KP;
    int kp = rem - v * KP;
    int gate = v & 3, j = v >> 2;
    const float* W = dir ? Wb : Wf;
    int k = kp * 2;
    float x = 0.f, y = 0.f;
    if (j < HH) {
        const float* wr = W + (size_t)(gate * HH + j) * HH;
        if (k     < HH) x = wr[k];
        if (k + 1 < HH) y = wr[k + 1];
    }
    unsigned lo, hi = pack_hilo(x, y, lo);
    g_whhH[i] = hi;
    g_whhL[i] = lo;
}

// ---------------- interleaved bias sum ----------------
__global__ void bias_prep(const float* __restrict__ bih_f, const float* __restrict__ bhh_f,
                          const float* __restrict__ bih_b, const float* __restrict__ bhh_b) {
    int i = blockIdx.x * blockDim.x + threadIdx.x;
    if (i >= 2 * NPAD) return;
    int dir = i / NPAD;
    int v   = i - dir * NPAD;
    int gate = v & 3, j = v >> 2;
    float b = 0.f;
    if (j < HH) {
        const float* bi = dir ? bih_b : bih_f;
        const float* bh = dir ? bhh_b : bhh_f;
        b = bi[gate * HH + j] + bh[gate * HH + j];
    }
    g_bsum[i] = b;
}

#define PADW 136

// ---------------- recurrence GEMM + fused LSTM gates ----------------
// grid (10, 16, 2), block 256, 2 CTAs/SM. One launch per timestep.
// Reads h from buffer (s&1), writes h to buffer (s&1)^1 -> no intra-launch race.
__global__ void __launch_bounds__(256, 2)
gemm_rec(int s)
{
    __shared__ __align__(16) unsigned AsH[2][8 * PADW];
    __shared__ __align__(16) unsigned AsL[2][8 * PADW];
    __shared__ __align__(16) unsigned BsH[2][8 * PADW];
    __shared__ __align__(16) unsigned BsL[2][8 * PADW];

    const int t    = threadIdx.x;
    const int dir  = blockIdx.z;
    const int bm   = blockIdx.y * 128;
    const int bn   = blockIdx.x * 128;
    const int lr   = t & 127;
    const int half = t >> 7;           // 0/1 -> 4-kpair group within chunk
    const int wid  = t >> 5;
    const int wm   = wid >> 1;
    const int wn   = wid & 1;
    const int lane = t & 31;
    const int g    = lane >> 2;
    const int tig  = lane & 3;

    const int rbuf = s & 1;
    const int wbuf = rbuf ^ 1;

    const float* hfp = g_hf + ((size_t)rbuf * 2 + dir) * BB * HPAD + (size_t)(bm + lr) * HPAD;
    float* hout = g_hf + ((size_t)wbuf * 2 + dir) * BB * HPAD;
    const unsigned* wHp = g_whhH + ((size_t)(dir * NPAD + bn + lr)) * KP;
    const unsigned* wLp = g_whhL + ((size_t)(dir * NPAD + bn + lr)) * KP;

    float acc[2][8][4];
    #pragma unroll
    for (int i = 0; i < 2; i++)
        #pragma unroll
        for (int j = 0; j < 8; j++)
            #pragma unroll
            for (int q = 0; q < 4; q++) acc[i][j][q] = 0.0f;

    uint4 aH, aL, bH, bL;
    auto gload = [&](int chunk) {
        int kp0 = chunk * 8 + half * 4;
        float4 f0 = *(const float4*)(hfp + kp0 * 2);
        float4 f1 = *(const float4*)(hfp + kp0 * 2 + 4);
        aH.x = pack_hilo(f0.x, f0.y, aL.x);
        aH.y = pack_hilo(f0.z, f0.w, aL.y);
        aH.z = pack_hilo(f1.x, f1.y, aL.z);
        aH.w = pack_hilo(f1.z, f1.w, aL.w);
        bH = *(const uint4*)(wHp + kp0);
        bL = *(const uint4*)(wLp + kp0);
    };
    auto sts = [&](int buf) {
        int p0 = half * 4;
        AsH[buf][(p0 + 0) * PADW + lr] = aH.x;
        AsH[buf][(p0 + 1) * PADW + lr] = aH.y;
        AsH[buf][(p0 + 2) * PADW + lr] = aH.z;
        AsH[buf][(p0 + 3) * PADW + lr] = aH.w;
        AsL[buf][(p0 + 0) * PADW + lr] = aL.x;
        AsL[buf][(p0 + 1) * PADW + lr] = aL.y;
        AsL[buf][(p0 + 2) * PADW + lr] = aL.z;
        AsL[buf][(p0 + 3) * PADW + lr] = aL.w;
        BsH[buf][(p0 + 0) * PADW + lr] = bH.x;
        BsH[buf][(p0 + 1) * PADW + lr] = bH.y;
        BsH[buf][(p0 + 2) * PADW + lr] = bH.z;
        BsH[buf][(p0 + 3) * PADW + lr] = bH.w;
        BsL[buf][(p0 + 0) * PADW + lr] = bL.x;
        BsL[buf][(p0 + 1) * PADW + lr] = bL.y;
        BsL[buf][(p0 + 2) * PADW + lr] = bL.z;
        BsL[buf][(p0 + 3) * PADW + lr] = bL.w;
    };

    gload(0);
    sts(0);
    __syncthreads();

    int cur = 0;
    for (int c = 0; c < 19; c++) {
        bool more = (c + 1) < 19;
        if (more) gload(c + 1);

        unsigned bh[8][2], bl[8][2];
        #pragma unroll
        for (int nt = 0; nt < 8; nt++) {
            int col = wn * 64 + nt * 8 + g;
            bh[nt][0] = BsH[cur][tig * PADW + col];
            bh[nt][1] = BsH[cur][(tig + 4) * PADW + col];
            bl[nt][0] = BsL[cur][tig * PADW + col];
            bl[nt][1] = BsL[cur][(tig + 4) * PADW + col];
        }
        #pragma unroll
        for (int mt = 0; mt < 2; mt++) {
            int row = wm * 32 + mt * 16 + g;
            unsigned ah[4], al[4];
            ah[0] = AsH[cur][tig * PADW + row];
            ah[1] = AsH[cur][tig * PADW + row + 8];
            ah[2] = AsH[cur][(tig + 4) * PADW + row];
            ah[3] = AsH[cur][(tig + 4) * PADW + row + 8];
            al[0] = AsL[cur][tig * PADW + row];
            al[1] = AsL[cur][tig * PADW + row + 8];
            al[2] = AsL[cur][(tig + 4) * PADW + row];
            al[3] = AsL[cur][(tig + 4) * PADW + row + 8];
            #pragma unroll
            for (int nt = 0; nt < 8; nt++) {
                mma_bf16(acc[mt][nt], ah, bh[nt]);  // hi*hi
                mma_bf16(acc[mt][nt], al, bh[nt]);  // lo*hi
                mma_bf16(acc[mt][nt], ah, bl[nt]);  // hi*lo
            }
        }

        if (more) sts(cur ^ 1);
        __syncthreads();
        cur ^= 1;
    }

    // ---- fused LSTM-gate epilogue ----
    // Interleaved cols: v = 4j+gate. tig{0,1} hold (i,f)/(g,o) of quad A,
    // tig{2,3} of quad B. shfl.xor 1 gives even lanes all four gates.
    const int tt = dir ? (TT - 1 - s) : s;
    #pragma unroll
    for (int mt = 0; mt < 2; mt++) {
        #pragma unroll
        for (int nt = 0; nt < 8; nt++) {
            float v0 = acc[mt][nt][0], v1 = acc[mt][nt][1];
            float v2 = acc[mt][nt][2], v3 = acc[mt][nt][3];
            float p0 = __shfl_xor_sync(0xffffffffu, v0, 1);
            float p1 = __shfl_xor_sync(0xffffffffu, v1, 1);
            float p2 = __shfl_xor_sync(0xffffffffu, v2, 1);
            float p3 = __shfl_xor_sync(0xffffffffu, v3, 1);
            if ((tig & 1) == 0) {
                int colbase = bn + wn * 64 + nt * 8 + (tig >> 1) * 4;
                int j = colbase >> 2;
                if (j < HH) {
                    int r0 = bm + wm * 32 + mt * 16 + g;
                    #pragma unroll
                    for (int h2 = 0; h2 < 2; h2++) {
                        int r = r0 + h2 * 8;
                        float ai = h2 ? v2 : v0;
                        float af = h2 ? v3 : v1;
                        float ag = h2 ? p2 : p0;
                        float ao = h2 ? p3 : p1;
                        float4 gi4 = *(const float4*)&g_gi[(size_t)dir * BT * NPAD
                                       + ((size_t)r * TT + tt) * NPAD + colbase];
                        float4 bs4 = *(const float4*)&g_bsum[(size_t)dir * NPAD + colbase];
                        float xi = ai + gi4.x + bs4.x;
                        float xf = af + gi4.y + bs4.y;
                        float xg = ag + gi4.z + bs4.z;
                        float xo = ao + gi4.w + bs4.w;
                        float ig = sigf(xi), fg = sigf(xf);
                        float cg = tanhfast(xg), og = sigf(xo);
                        size_t ci = (size_t)dir * BB * HH + (size_t)r * HH + j;
                        float cn = fg * g_cs[ci] + ig * cg;
                        float hn = og * tanhfast(cn);
                        g_cs[ci] = cn;
                        g_c[((size_t)r * TT + tt) * D2 + dir * HH + j] = hn;
                        hout[(size_t)r * HPAD + j] = hn;
                    }
                }
            }
        }
    }
}

// ---------------- tensor-core GEMM (3xBF16, ~fp32-accurate) ----------------
// GPERM: NT B-row v maps to physical row (v&3)*HH + (v>>2), zero if (v>>2)>=HH
template<int BLAY, int MODK, int BIASF, int SPLITK, int GIDX, int GPERM>
__global__ void __launch_bounds__(256, 2)
gemm_bf(const float* __restrict__ A0, const float* __restrict__ B0, float* __restrict__ C0,
        const float* __restrict__ A1, const float* __restrict__ B1, float* __restrict__ C1,
        const float* __restrict__ bias, const int* __restrict__ gidx,
        int M, int N, int K)
{
    __shared__ __align__(16) unsigned AsH[2][8 * PADW];
    __shared__ __align__(16) unsigned AsL[2][8 * PADW];
    __shared__ __align__(16) unsigned BsH[2][8 * PADW];
    __shared__ __align__(16) unsigned BsL[2][8 * PADW];

    const float* A; const float* Bm; float* C;
    int kbeg, kend;
    if (SPLITK > 1) {
        A = A0; Bm = B0; C = C0;
        int ks = K / SPLITK;
        kbeg = blockIdx.z * ks;
        kend = kbeg + ks;
    } else {
        A  = blockIdx.z ? A1 : A0;
        Bm = blockIdx.z ? B1 : B0;
        C  = blockIdx.z ? C1 : C0;
        kbeg = 0; kend = K;
    }

    const int t  = threadIdx.x;
    const int bm = blockIdx.y * 128;
    const int bn = blockIdx.x * 128;

    const int lr = t & 127;
    const int lk = (t >> 7) * 8;
    const int lp = t >> 5;
    const int lc = (t & 31) * 4;

    const int wid  = t >> 5;
    const int wm   = wid >> 1;
    const int wn   = wid & 1;
    const int lane = t & 31;
    const int g   = lane >> 2;
    const int tig = lane & 3;

    float acc[2][8][4];
    #pragma unroll
    for (int i = 0; i < 2; i++)
        #pragma unroll
        for (int j = 0; j < 8; j++)
            #pragma unroll
            for (int q = 0; q < 4; q++) acc[i][j][q] = 0.0f;

    float4 ra[2], rb[2];

    auto gload = [&](int k0) {
        {
            int row = bm + lr;
            const float* ap = nullptr;
            if (row < M) {
                long arow = GIDX ? (long)gidx[row] : (long)row;
                ap = A + (size_t)arow * K;
            }
            #pragma unroll
            for (int q = 0; q < 2; q++) {
                int k = k0 + lk + q * 4;
                float4 v = make_float4(0.f, 0.f, 0.f, 0.f);
                if (ap) {
                    if (k + 3 < kend) v = *(const float4*)(ap + k);
                    else {
                        if (k     < kend) v.x = ap[k];
                        if (k + 1 < kend) v.y = ap[k + 1];
                        if (k + 2 < kend) v.z = ap[k + 2];
                    }
                }
                ra[q] = v;
            }
        }
        if (BLAY == 0) {
            int row = bn + lr;
            const float* bp = nullptr;
            if (row < N) {
                if (GPERM) {
                    int gate = row & 3, j = row >> 2;
                    if (j < HH) bp = Bm + (size_t)(gate * HH + j) * K;
                } else if (MODK == 0) {
                    bp = Bm + (size_t)row * K;
                }
            }
            #pragma unroll
            for (int q = 0; q < 2; q++) {
                int k = k0 + lk + q * 4;
                float4 v = make_float4(0.f, 0.f, 0.f, 0.f);
                if (MODK > 0) {
                    if (row < N) v = *(const float4*)(Bm + (size_t)row * MODK + (k % MODK));
                } else if (bp) {
                    if (k + 3 < kend) v = *(const float4*)(bp + k);
                    else {
                        if (k     < kend) v.x = bp[k];
                        if (k + 1 < kend) v.y = bp[k + 1];
                        if (k + 2 < kend) v.z = bp[k + 2];
                    }
                }
                rb[q] = v;
            }
        } else {
            #pragma unroll
            for (int q = 0; q < 2; q++) {
                int k = k0 + 2 * lp + q;
                float4 v = make_float4(0.f, 0.f, 0.f, 0.f);
                if (k < kend) {
                    const float* bp = Bm + (size_t)k * N;
                    int col = bn + lc;
                    if (col + 3 < N) v = *(const float4*)(bp + col);
                    else {
                        if (col     < N) v.x = bp[col];
                        if (col + 1 < N) v.y = bp[col + 1];
                        if (col + 2 < N) v.z = bp[col + 2];
                    }
                }
                rb[q] = v;
            }
        }
    };

    auto sts = [&](int buf) {
        #pragma unroll
        for (int q = 0; q < 2; q++) {
            int p = (lk >> 1) + 2 * q;
            unsigned lo0, lo1;
            unsigned h0 = pack_hilo(ra[q].x, ra[q].y, lo0);
            unsigned h1 = pack_hilo(ra[q].z, ra[q].w, lo1);
            AsH[buf][p * PADW + lr]       = h0;
            AsL[buf][p * PADW + lr]       = lo0;
            AsH[buf][(p + 1) * PADW + lr] = h1;
            AsL[buf][(p + 1) * PADW + lr] = lo1;
        }
        if (BLAY == 0) {
            #pragma unroll
            for (int q = 0; q < 2; q++) {
                int p = (lk >> 1) + 2 * q;
                unsigned lo0, lo1;
                unsigned h0 = pack_hilo(rb[q].x, rb[q].y, lo0);
                unsigned h1 = pack_hilo(rb[q].z, rb[q].w, lo1);
                BsH[buf][p * PADW + lr]       = h0;
                BsL[buf][p * PADW + lr]       = lo0;
                BsH[buf][(p + 1) * PADW + lr] = h1;
                BsL[buf][(p + 1) * PADW + lr] = lo1;
            }
        } else {
            uint4 h4, l4;
            h4.x = pack_hilo(rb[0].x, rb[1].x, l4.x);
            h4.y = pack_hilo(rb[0].y, rb[1].y, l4.y);
            h4.z = pack_hilo(rb[0].z, rb[1].z, l4.z);
            h4.w = pack_hilo(rb[0].w, rb[1].w, l4.w);
            *(uint4*)&BsH[buf][lp * PADW + lc] = h4;
            *(uint4*)&BsL[buf][lp * PADW + lc] = l4;
        }
    };

    gload(kbeg);
    sts(0);
    __syncthreads();

    int cur = 0;
    for (int k0 = kbeg; k0 < kend; k0 += 16) {
        bool more = (k0 + 16) < kend;
        if (more) gload(k0 + 16);

        unsigned bh[8][2], bl[8][2];
        #pragma unroll
        for (int nt = 0; nt < 8; nt++) {
            int col = wn * 64 + nt * 8 + g;
            bh[nt][0] = BsH[cur][tig * PADW + col];
            bh[nt][1] = BsH[cur][(tig + 4) * PADW + col];
            bl[nt][0] = BsL[cur][tig * PADW + col];
            bl[nt][1] = BsL[cur][(tig + 4) * PADW + col];
        }
        #pragma unroll
        for (int mt = 0; mt < 2; mt++) {
            int row = wm * 32 + mt * 16 + g;
            unsigned ah[4], al[4];
            ah[0] = AsH[cur][tig * PADW + row];
            ah[1] = AsH[cur][tig * PADW + row + 8];
            ah[2] = AsH[cur][(tig + 4) * PADW + row];
            ah[3] = AsH[cur][(tig + 4) * PADW + row + 8];
            al[0] = AsL[cur][tig * PADW + row];
            al[1] = AsL[cur][tig * PADW + row + 8];
            al[2] = AsL[cur][(tig + 4) * PADW + row];
            al[3] = AsL[cur][(tig + 4) * PADW + row + 8];
            #pragma unroll
            for (int nt = 0; nt < 8; nt++) {
                mma_bf16(acc[mt][nt], ah, bh[nt]);
                mma_bf16(acc[mt][nt], al, bh[nt]);
                mma_bf16(acc[mt][nt], ah, bl[nt]);
            }
        }

        if (more) sts(cur ^ 1);
        __syncthreads();
        cur ^= 1;
    }

    #pragma unroll
    for (int mt = 0; mt < 2; mt++) {
        #pragma unroll
        for (int nt = 0; nt < 8; nt++) {
            int row0 = bm + wm * 32 + mt * 16 + g;
            int col0 = bn + wn * 64 + nt * 8 + tig * 2;
            #pragma unroll
            for (int h = 0; h < 2; h++) {
                int row = row0 + h * 8;
                if (row < M) {
                    #pragma unroll
                    for (int w = 0; w < 2; w++) {
                        int col = col0 + w;
                        if (col < N) {
                            float v = acc[mt][nt][h * 2 + w];
                            if (BIASF) v += bias[col];
                            if (SPLITK > 1) atomicAdd(&C[(size_t)row * N + col], v);
                            else            C[(size_t)row * N + col] = v;
                        }
                    }
                }
            }
        }
    }
}

// ---------------- row L2-normalize (warp per row) ----------------
__global__ void rownorm(const float* __restrict__ in, float* __restrict__ out, int R, int W) {
    int warp = threadIdx.x >> 5;
    int lane = threadIdx.x & 31;
    int row = blockIdx.x * 8 + warp;
    if (row >= R) return;
    const float* p = in + (size_t)row * W;
    float ss = 0.f;
    for (int cc = lane; cc < W; cc += 32) { float v = p[cc]; ss += v * v; }
    #pragma unroll
    for (int o = 16; o; o >>= 1) ss += __shfl_xor_sync(0xffffffffu, ss, o);
    float scale = 1.0f / fmaxf(sqrtf(ss), 1e-8f);
    float* q = out + (size_t)row * W;
    for (int cc = lane; cc < W; cc += 32) q[cc] = p[cc] * scale;
}

// ---------------- edge scatter-add: agg[dst] += m[src] ----------------
__global__ void scatter_add(const int* __restrict__ ei) {
    int i = blockIdx.x * blockDim.x + threadIdx.x;
    if (i >= NEDGE * (CC / 4)) return;
    int e  = i >> 8;
    int c4 = (i & 255) << 2;
    int src = ei[e];
    int dst = ei[NEDGE + e];
    float4 v = *(const float4*)&g_m[(size_t)src * CC + c4];
    float* a = &g_agg[(size_t)dst * CC + c4];
    atomicAdd(a + 0, v.x); atomicAdd(a + 1, v.y);
    atomicAdd(a + 2, v.z); atomicAdd(a + 3, v.w);
}

// ---------------- GRU cell update (in-place on g_hn) ----------------
__global__ void gru_gates(const float* __restrict__ bih, const float* __restrict__ bhh) {
    int i = blockIdx.x * blockDim.x + threadIdx.x;
    if (i >= BB * CC) return;
    int b = i >> 10;
    int j = i & 1023;
    size_t gb = (size_t)b * 3072;
    size_t gh = (size_t)BB * 3072 + gb;

    float ir  = g_gru[gb +        j] + bih[j];
    float iz  = g_gru[gb + 1024 + j] + bih[1024 + j];
    float in_ = g_gru[gb + 2048 + j] + bih[2048 + j];
    float hr  = g_gru[gh +        j] + bhh[j];
    float hz  = g_gru[gh + 1024 + j] + bhh[1024 + j];
    float hn  = g_gru[gh + 2048 + j] + bhh[2048 + j];

    float rg = sigf(ir + hr);
    float zg = sigf(iz + hz);
    float ng = tanhfast(in_ + rg * hn);
    float h = g_hn[i];
    g_hn[i] = (1.0f - zg) * ng + zg * h;
}

// ---------------- orchestration ----------------
extern "C" void kernel_launch(void* const* d_in, const int* in_sizes, int n_in,
                              void* d_out, int out_size)
{
    const int*   x        = (const int*)d_in[0];
    const int*   ei       = (const int*)d_in[1];
    const float* emb_tab  = (const float*)d_in[2];
    const float* Wih_f    = (const float*)d_in[3];
    const float* Whh_f    = (const float*)d_in[4];
    const float* bih_f    = (const float*)d_in[5];
    const float* bhh_f    = (const float*)d_in[6];
    const float* Wih_b    = (const float*)d_in[7];
    const float* Whh_b    = (const float*)d_in[8];
    const float* bih_b    = (const float*)d_in[9];
    const float* bhh_b    = (const float*)d_in[10];
    const float* label    = (const float*)d_in[11];
    const float* ggc_w    = (const float*)d_in[12];
    const float* gru_Wih  = (const float*)d_in[13];
    const float* gru_Whh  = (const float*)d_in[14];
    const float* gru_bih  = (const float*)d_in[15];
    const float* gru_bhh  = (const float*)d_in[16];
    const float* proj_W   = (const float*)d_in[17];
    const float* proj_b   = (const float*)d_in[18];
    float* out = (float*)d_out;

    float *p_gi, *p_c, *p_cs, *p_hf, *p_lnn, *p_hn, *p_m, *p_agg, *p_gru;
    cudaGetSymbolAddress((void**)&p_gi,  g_gi);
    cudaGetSymbolAddress((void**)&p_c,   g_c);
    cudaGetSymbolAddress((void**)&p_cs,  g_cs);
    cudaGetSymbolAddress((void**)&p_hf,  g_hf);
    cudaGetSymbolAddress((void**)&p_lnn, g_lnn);
    cudaGetSymbolAddress((void**)&p_hn,  g_hn);
    cudaGetSymbolAddress((void**)&p_m,   g_m);
    cudaGetSymbolAddress((void**)&p_agg, g_agg);
    cudaGetSymbolAddress((void**)&p_gru, g_gru);

    const int TPB = 256;

    // 0) init state; pre-split Whh (interleaved); bias sums
    zerok<<<(2 * BB * HH + TPB - 1) / TPB, TPB>>>(p_cs, 2 * BB * HH);
    zerok<<<(2 * 2 * BB * HPAD + TPB - 1) / TPB, TPB>>>(p_hf, 2 * 2 * BB * HPAD);
    split_whh<<<(2 * NPAD * KP + TPB - 1) / TPB, TPB>>>(Whh_f, Whh_b);
    bias_prep<<<(2 * NPAD + TPB - 1) / TPB, TPB>>>(bih_f, bhh_f, bih_b, bhh_b);

    // 1) input-to-hidden GEMMs, fused embedding gather, interleaved output
    {
        dim3 grid(NPAD / 128, (BT + 127) / 128, 2);
        gemm_bf<0, 0, 0, 1, 1, 1><<<grid, 256>>>(emb_tab, Wih_f, p_gi,
                                                 emb_tab, Wih_b, p_gi + (size_t)BT * NPAD,
                                                 nullptr, x, BT, NPAD, EE);
    }

    // 2) recurrence: 64 steps, ONE fused launch per step (double-buffered h)
    for (int s = 0; s < TT; s++) {
        dim3 grid(NPAD / 128, BB / 128, 2);
        gemm_rec<<<grid, 256>>>(s);
    }

    // 3) normalize c rows (in place) and label rows
    rownorm<<<(BT + 7) / 8, 256>>>(p_c, p_c, BT, D2);
    rownorm<<<(CC + 7) / 8, 256>>>(label, p_lnn, CC, D2);

    // 4) cosine similarity folded GEMM: [B, 38400] x periodic [1024, 600], split-K x4
    zerok<<<(BB * CC + TPB - 1) / TPB, TPB>>>(p_hn, BB * CC);
    {
        dim3 grid((CC + 127) / 128, (BB + 127) / 128, 4);
        gemm_bf<0, D2, 0, 4, 0, 0><<<grid, 256>>>(p_c, p_lnn, p_hn,
                                                  p_c, p_lnn, p_hn,
                                                  nullptr, nullptr, BB, CC, KCOS);
    }

    // 5) GatedGraphConv, 2 layers
    for (int layer = 0; layer < 2; layer++) {
        {
            dim3 grid((CC + 127) / 128, (BB + 127) / 128, 1);
            gemm_bf<1, 0, 0, 1, 0, 0><<<grid, 256>>>(p_hn, ggc_w + (size_t)layer * CC * CC, p_m,
                                                     p_hn, ggc_w + (size_t)layer * CC * CC, p_m,
                                                     nullptr, nullptr, BB, CC, CC);
        }
        zerok<<<(BB * CC + TPB - 1) / TPB, TPB>>>(p_agg, BB * CC);
        scatter_add<<<(NEDGE * (CC / 4) + TPB - 1) / TPB, TPB>>>(ei);
        {
            dim3 grid((3072 + 127) / 128, (BB + 127) / 128, 2);
            gemm_bf<0, 0, 0, 1, 0, 0><<<grid, 256>>>(p_agg, gru_Wih, p_gru,
                                                     p_hn,  gru_Whh, p_gru + (size_t)BB * 3072,
                                                     nullptr, nullptr, BB, 3072, CC);
        }
        gru_gates<<<(BB * CC + TPB - 1) / TPB, TPB>>>(gru_bih, gru_bhh);
    }

    // 6) projection with bias -> d_out
    {
        dim3 grid((CC + 127) / 128, (BB + 127) / 128, 1);
        gemm_bf<0, 0, 1, 1, 0, 0><<<grid, 256>>>(p_hn, proj_W, out,
                                                 p_hn, proj_W, out,
                                                 proj_b, nullptr, BB, CC, CC);
    }
}

// round 12
// speedup vs baseline: 1.3265x; 1.3265x over previous
#include <cuda_runtime.h>
#include <cuda_bf16.h>

// ---------------- problem constants ----------------
#define BB   2048          // batch / num nodes
#define TT   64            // seq len
#define EE   300           // embed dim = hidden
#define HH   300
#define G4   1200          // 4*H
#define D2   600           // 2*H
#define CC   1024          // num classes
#define NEDGE 65536
#define BT   (BB*TT)       // 131072
#define KCOS (TT*D2)       // 38400
#define KP   152           // k-pairs for H=300 padded to 304

// ---------------- scratch (device globals; no cudaMalloc allowed) ----------------
__device__ float g_gi [(size_t)2 * BT * G4];
__device__ float g_c  [(size_t)BT * D2];
__device__ float g_cs [(size_t)2 * BB * HH];
__device__ float g_gg [(size_t)2 * BB * G4];
__device__ float g_lnn[(size_t)CC * D2];
__device__ float g_hn [(size_t)BB * CC];
__device__ float g_m  [(size_t)BB * CC];
__device__ float g_agg[(size_t)BB * CC];
__device__ float g_gru[(size_t)2 * BB * 3072];
// pre-split bf16x2 hi/lo: h state and Whh weights, layout [dir][row][kpair]
__device__ unsigned g_hH  [(size_t)2 * BB * KP];
__device__ unsigned g_hL  [(size_t)2 * BB * KP];
__device__ unsigned g_whhH[(size_t)2 * G4 * KP];
__device__ unsigned g_whhL[(size_t)2 * G4 * KP];

// ---------------- helpers ----------------
__device__ __forceinline__ float sigf(float x) { return 1.0f / (1.0f + __expf(-x)); }
__device__ __forceinline__ float tanhfast(float x) {
    return 2.0f / (1.0f + __expf(-2.0f * x)) - 1.0f;
}

__global__ void zerok(float* __restrict__ p, int n) {
    int i = blockIdx.x * blockDim.x + threadIdx.x;
    if (i < n) p[i] = 0.0f;
}

// ---------------- bf16 split helpers ----------------
__device__ __forceinline__ unsigned pack_hilo(float x, float y, unsigned& lo) {
    __nv_bfloat16 hx = __float2bfloat16_rn(x);
    __nv_bfloat16 hy = __float2bfloat16_rn(y);
    __nv_bfloat16 lx = __float2bfloat16_rn(x - __bfloat162float(hx));
    __nv_bfloat16 ly = __float2bfloat16_rn(y - __bfloat162float(hy));
    __nv_bfloat162 h2 = __halves2bfloat162(hx, hy);
    __nv_bfloat162 l2 = __halves2bfloat162(lx, ly);
    lo = *reinterpret_cast<unsigned*>(&l2);
    return *reinterpret_cast<unsigned*>(&h2);
}

__device__ __forceinline__ void mma_bf16(float* d, const unsigned* a, const unsigned* b) {
    asm volatile(
        "mma.sync.aligned.m16n8k16.row.col.f32.bf16.bf16.f32 "
        "{%0,%1,%2,%3},{%4,%5,%6,%7},{%8,%9},{%0,%1,%2,%3};\n"
        : "+f"(d[0]), "+f"(d[1]), "+f"(d[2]), "+f"(d[3])
        : "r"(a[0]), "r"(a[1]), "r"(a[2]), "r"(a[3]),
          "r"(b[0]), "r"(b[1]));
}

// ---------------- pre-split Whh into packed bf16x2 hi/lo ----------------
__global__ void split_whh(const float* __restrict__ Wf, const float* __restrict__ Wb) {
    int i = blockIdx.x * blockDim.x + threadIdx.x;
    if (i >= 2 * G4 * KP) return;
    int dir = i / (G4 * KP);
    int rem = i - dir * (G4 * KP);
    int n  = rem / KP;
    int kp = rem - n * KP;
    const float* W = dir ? Wb : Wf;
    int k = kp * 2;
    float x = (k     < HH) ? W[(size_t)n * HH + k]     : 0.f;
    float y = (k + 1 < HH) ? W[(size_t)n * HH + k + 1] : 0.f;
    unsigned lo, hi = pack_hilo(x, y, lo);
    g_whhH[i] = hi;
    g_whhL[i] = lo;
}

#define PADW 136

// ---------------- recurrence GEMM: gg[dir] = h[dir] @ Whh[dir]^T (pre-split) ----------------
// grid (10, 16, 2), block 256, 2 CTAs/SM
__global__ void __launch_bounds__(256, 2)
gemm_rec()
{
    __shared__ __align__(16) unsigned AsH[2][8 * PADW];
    __shared__ __align__(16) unsigned AsL[2][8 * PADW];
    __shared__ __align__(16) unsigned BsH[2][8 * PADW];
    __shared__ __align__(16) unsigned BsL[2][8 * PADW];

    const int t    = threadIdx.x;
    const int dir  = blockIdx.z;
    const int bm   = blockIdx.y * 128;
    const int bn   = blockIdx.x * 128;
    const int lr   = t & 127;
    const int half = t >> 7;           // 0/1 -> 4-kpair group within chunk
    const int wid  = t >> 5;
    const int wm   = wid >> 1;
    const int wn   = wid & 1;
    const int lane = t & 31;
    const int g    = lane >> 2;
    const int tig  = lane & 3;

    const unsigned* hHp = g_hH + ((size_t)(dir * BB + bm + lr)) * KP;
    const unsigned* hLp = g_hL + ((size_t)(dir * BB + bm + lr)) * KP;
    const int brow = bn + lr;
    const unsigned* wHp = (brow < G4) ? g_whhH + ((size_t)(dir * G4 + brow)) * KP : nullptr;
    const unsigned* wLp = (brow < G4) ? g_whhL + ((size_t)(dir * G4 + brow)) * KP : nullptr;

    float acc[2][8][4];
    #pragma unroll
    for (int i = 0; i < 2; i++)
        #pragma unroll
        for (int j = 0; j < 8; j++)
            #pragma unroll
            for (int q = 0; q < 4; q++) acc[i][j][q] = 0.0f;

    uint4 aH, aL, bH, bL;
    auto gload = [&](int chunk) {
        int kp0 = chunk * 8 + half * 4;
        aH = *(const uint4*)(hHp + kp0);
        aL = *(const uint4*)(hLp + kp0);
        if (wHp) {
            bH = *(const uint4*)(wHp + kp0);
            bL = *(const uint4*)(wLp + kp0);
        } else {
            bH = make_uint4(0u, 0u, 0u, 0u);
            bL = make_uint4(0u, 0u, 0u, 0u);
        }
    };
    auto sts = [&](int buf) {
        int p0 = half * 4;
        AsH[buf][(p0 + 0) * PADW + lr] = aH.x;
        AsH[buf][(p0 + 1) * PADW + lr] = aH.y;
        AsH[buf][(p0 + 2) * PADW + lr] = aH.z;
        AsH[buf][(p0 + 3) * PADW + lr] = aH.w;
        AsL[buf][(p0 + 0) * PADW + lr] = aL.x;
        AsL[buf][(p0 + 1) * PADW + lr] = aL.y;
        AsL[buf][(p0 + 2) * PADW + lr] = aL.z;
        AsL[buf][(p0 + 3) * PADW + lr] = aL.w;
        BsH[buf][(p0 + 0) * PADW + lr] = bH.x;
        BsH[buf][(p0 + 1) * PADW + lr] = bH.y;
        BsH[buf][(p0 + 2) * PADW + lr] = bH.z;
        BsH[buf][(p0 + 3) * PADW + lr] = bH.w;
        BsL[buf][(p0 + 0) * PADW + lr] = bL.x;
        BsL[buf][(p0 + 1) * PADW + lr] = bL.y;
        BsL[buf][(p0 + 2) * PADW + lr] = bL.z;
        BsL[buf][(p0 + 3) * PADW + lr] = bL.w;
    };

    gload(0);
    sts(0);
    __syncthreads();

    int cur = 0;
    for (int c = 0; c < 19; c++) {
        bool more = (c + 1) < 19;
        if (more) gload(c + 1);

        unsigned bh[8][2], bl[8][2];
        #pragma unroll
        for (int nt = 0; nt < 8; nt++) {
            int col = wn * 64 + nt * 8 + g;
            bh[nt][0] = BsH[cur][tig * PADW + col];
            bh[nt][1] = BsH[cur][(tig + 4) * PADW + col];
            bl[nt][0] = BsL[cur][tig * PADW + col];
            bl[nt][1] = BsL[cur][(tig + 4) * PADW + col];
        }
        #pragma unroll
        for (int mt = 0; mt < 2; mt++) {
            int row = wm * 32 + mt * 16 + g;
            unsigned ah[4], al[4];
            ah[0] = AsH[cur][tig * PADW + row];
            ah[1] = AsH[cur][tig * PADW + row + 8];
            ah[2] = AsH[cur][(tig + 4) * PADW + row];
            ah[3] = AsH[cur][(tig + 4) * PADW + row + 8];
            al[0] = AsL[cur][tig * PADW + row];
            al[1] = AsL[cur][tig * PADW + row + 8];
            al[2] = AsL[cur][(tig + 4) * PADW + row];
            al[3] = AsL[cur][(tig + 4) * PADW + row + 8];
            #pragma unroll
            for (int nt = 0; nt < 8; nt++) {
                mma_bf16(acc[mt][nt], ah, bh[nt]);  // hi*hi
                mma_bf16(acc[mt][nt], al, bh[nt]);  // lo*hi
                mma_bf16(acc[mt][nt], ah, bl[nt]);  // hi*lo
            }
        }

        if (more) sts(cur ^ 1);
        __syncthreads();
        cur ^= 1;
    }

    float* Cp = g_gg + (size_t)dir * BB * G4;
    #pragma unroll
    for (int mt = 0; mt < 2; mt++) {
        #pragma unroll
        for (int nt = 0; nt < 8; nt++) {
            int row0 = bm + wm * 32 + mt * 16 + g;
            int col0 = bn + wn * 64 + nt * 8 + tig * 2;
            #pragma unroll
            for (int h2 = 0; h2 < 2; h2++) {
                int row = row0 + h2 * 8;
                #pragma unroll
                for (int w = 0; w < 2; w++) {
                    int col = col0 + w;
                    if (col < G4)
                        Cp[(size_t)row * G4 + col] = acc[mt][nt][h2 * 2 + w];
                }
            }
        }
    }
}

// ---------------- LSTM gates: pointwise + write split h ----------------
__global__ void lstm_gates(const float* __restrict__ bih_f, const float* __restrict__ bhh_f,
                           const float* __restrict__ bih_b, const float* __restrict__ bhh_b,
                           int s)
{
    int p = blockIdx.x * blockDim.x + threadIdx.x;
    if (p >= 2 * BB * KP) return;
    int dir = p / (BB * KP);
    int rem = p - dir * (BB * KP);
    int b   = rem / KP;
    int kp  = rem - b * KP;
    int j0  = kp * 2;
    int tt  = dir ? (TT - 1 - s) : s;

    float h0 = 0.f, h1 = 0.f;
    if (j0 < HH) {
        const float* bi = dir ? bih_b : bih_f;
        const float* bh = dir ? bhh_b : bhh_f;
        size_t gg = (size_t)dir * BB * G4 + (size_t)b * G4;
        size_t gi = (size_t)dir * BT * G4 + ((size_t)b * TT + tt) * G4;
        #pragma unroll
        for (int u = 0; u < 2; u++) {
            int j = j0 + u;
            float xi = g_gg[gg +         j] + g_gi[gi +         j] + bi[j]        + bh[j];
            float xf = g_gg[gg +  HH   + j] + g_gi[gi +  HH   + j] + bi[HH + j]   + bh[HH + j];
            float xg = g_gg[gg + 2*HH  + j] + g_gi[gi + 2*HH  + j] + bi[2*HH + j] + bh[2*HH + j];
            float xo = g_gg[gg + 3*HH  + j] + g_gi[gi + 3*HH  + j] + bi[3*HH + j] + bh[3*HH + j];
            float ig = sigf(xi), fg = sigf(xf), cg = tanhfast(xg), og = sigf(xo);
            size_t ci = (size_t)dir * BB * HH + (size_t)b * HH + j;
            float cn = fg * g_cs[ci] + ig * cg;
            float hn = og * tanhfast(cn);
            g_cs[ci] = cn;
            g_c[((size_t)b * TT + tt) * D2 + dir * HH + j] = hn;
            if (u == 0) h0 = hn; else h1 = hn;
        }
    }
    unsigned lo, hi = pack_hilo(h0, h1, lo);
    g_hH[p] = hi;
    g_hL[p] = lo;
}

// ---------------- tensor-core GEMM (3xBF16, ~fp32-accurate) ----------------
template<int BLAY, int MODK, int BIASF, int SPLITK, int GIDX>
__global__ void __launch_bounds__(256, 2)
gemm_bf(const float* __restrict__ A0, const float* __restrict__ B0, float* __restrict__ C0,
        const float* __restrict__ A1, const float* __restrict__ B1, float* __restrict__ C1,
        const float* __restrict__ bias, const int* __restrict__ gidx,
        int M, int N, int K)
{
    __shared__ __align__(16) unsigned AsH[2][8 * PADW];
    __shared__ __align__(16) unsigned AsL[2][8 * PADW];
    __shared__ __align__(16) unsigned BsH[2][8 * PADW];
    __shared__ __align__(16) unsigned BsL[2][8 * PADW];

    const float* A; const float* Bm; float* C;
    int kbeg, kend;
    if (SPLITK > 1) {
        A = A0; Bm = B0; C = C0;
        int ks = K / SPLITK;
        kbeg = blockIdx.z * ks;
        kend = kbeg + ks;
    } else {
        A  = blockIdx.z ? A1 : A0;
        Bm = blockIdx.z ? B1 : B0;
        C  = blockIdx.z ? C1 : C0;
        kbeg = 0; kend = K;
    }

    const int t  = threadIdx.x;
    const int bm = blockIdx.y * 128;
    const int bn = blockIdx.x * 128;

    const int lr = t & 127;
    const int lk = (t >> 7) * 8;
    const int lp = t >> 5;
    const int lc = (t & 31) * 4;

    const int wid  = t >> 5;
    const int wm   = wid >> 1;
    const int wn   = wid & 1;
    const int lane = t & 31;
    const int g   = lane >> 2;
    const int tig = lane & 3;

    float acc[2][8][4];
    #pragma unroll
    for (int i = 0; i < 2; i++)
        #pragma unroll
        for (int j = 0; j < 8; j++)
            #pragma unroll
            for (int q = 0; q < 4; q++) acc[i][j][q] = 0.0f;

    float4 ra[2], rb[2];

    auto gload = [&](int k0) {
        {
            int row = bm + lr;
            const float* ap = nullptr;
            if (row < M) {
                long arow = GIDX ? (long)gidx[row] : (long)row;
                ap = A + (size_t)arow * K;
            }
            #pragma unroll
            for (int q = 0; q < 2; q++) {
                int k = k0 + lk + q * 4;
                float4 v = make_float4(0.f, 0.f, 0.f, 0.f);
                if (ap) {
                    if (k + 3 < kend) v = *(const float4*)(ap + k);
                    else {
                        if (k     < kend) v.x = ap[k];
                        if (k + 1 < kend) v.y = ap[k + 1];
                        if (k + 2 < kend) v.z = ap[k + 2];
                    }
                }
                ra[q] = v;
            }
        }
        if (BLAY == 0) {
            int row = bn + lr;
            #pragma unroll
            for (int q = 0; q < 2; q++) {
                int k = k0 + lk + q * 4;
                float4 v = make_float4(0.f, 0.f, 0.f, 0.f);
                if (row < N) {
                    if (MODK > 0) {
                        v = *(const float4*)(Bm + (size_t)row * MODK + (k % MODK));
                    } else {
                        const float* bp = Bm + (size_t)row * K;
                        if (k + 3 < kend) v = *(const float4*)(bp + k);
                        else {
                            if (k     < kend) v.x = bp[k];
                            if (k + 1 < kend) v.y = bp[k + 1];
                            if (k + 2 < kend) v.z = bp[k + 2];
                        }
                    }
                }
                rb[q] = v;
            }
        } else {
            #pragma unroll
            for (int q = 0; q < 2; q++) {
                int k = k0 + 2 * lp + q;
                float4 v = make_float4(0.f, 0.f, 0.f, 0.f);
                if (k < kend) {
                    const float* bp = Bm + (size_t)k * N;
                    int col = bn + lc;
                    if (col + 3 < N) v = *(const float4*)(bp + col);
                    else {
                        if (col     < N) v.x = bp[col];
                        if (col + 1 < N) v.y = bp[col + 1];
                        if (col + 2 < N) v.z = bp[col + 2];
                    }
                }
                rb[q] = v;
            }
        }
    };

    auto sts = [&](int buf) {
        #pragma unroll
        for (int q = 0; q < 2; q++) {
            int p = (lk >> 1) + 2 * q;
            unsigned lo0, lo1;
            unsigned h0 = pack_hilo(ra[q].x, ra[q].y, lo0);
            unsigned h1 = pack_hilo(ra[q].z, ra[q].w, lo1);
            AsH[buf][p * PADW + lr]       = h0;
            AsL[buf][p * PADW + lr]       = lo0;
            AsH[buf][(p + 1) * PADW + lr] = h1;
            AsL[buf][(p + 1) * PADW + lr] = lo1;
        }
        if (BLAY == 0) {
            #pragma unroll
            for (int q = 0; q < 2; q++) {
                int p = (lk >> 1) + 2 * q;
                unsigned lo0, lo1;
                unsigned h0 = pack_hilo(rb[q].x, rb[q].y, lo0);
                unsigned h1 = pack_hilo(rb[q].z, rb[q].w, lo1);
                BsH[buf][p * PADW + lr]       = h0;
                BsL[buf][p * PADW + lr]       = lo0;
                BsH[buf][(p + 1) * PADW + lr] = h1;
                BsL[buf][(p + 1) * PADW + lr] = lo1;
            }
        } else {
            uint4 h4, l4;
            h4.x = pack_hilo(rb[0].x, rb[1].x, l4.x);
            h4.y = pack_hilo(rb[0].y, rb[1].y, l4.y);
            h4.z = pack_hilo(rb[0].z, rb[1].z, l4.z);
            h4.w = pack_hilo(rb[0].w, rb[1].w, l4.w);
            *(uint4*)&BsH[buf][lp * PADW + lc] = h4;
            *(uint4*)&BsL[buf][lp * PADW + lc] = l4;
        }
    };

    gload(kbeg);
    sts(0);
    __syncthreads();

    int cur = 0;
    for (int k0 = kbeg; k0 < kend; k0 += 16) {
        bool more = (k0 + 16) < kend;
        if (more) gload(k0 + 16);

        unsigned bh[8][2], bl[8][2];
        #pragma unroll
        for (int nt = 0; nt < 8; nt++) {
            int col = wn * 64 + nt * 8 + g;
            bh[nt][0] = BsH[cur][tig * PADW + col];
            bh[nt][1] = BsH[cur][(tig + 4) * PADW + col];
            bl[nt][0] = BsL[cur][tig * PADW + col];
            bl[nt][1] = BsL[cur][(tig + 4) * PADW + col];
        }
        #pragma unroll
        for (int mt = 0; mt < 2; mt++) {
            int row = wm * 32 + mt * 16 + g;
            unsigned ah[4], al[4];
            ah[0] = AsH[cur][tig * PADW + row];
            ah[1] = AsH[cur][tig * PADW + row + 8];
            ah[2] = AsH[cur][(tig + 4) * PADW + row];
            ah[3] = AsH[cur][(tig + 4) * PADW + row + 8];
            al[0] = AsL[cur][tig * PADW + row];
            al[1] = AsL[cur][tig * PADW + row + 8];
            al[2] = AsL[cur][(tig + 4) * PADW + row];
            al[3] = AsL[cur][(tig + 4) * PADW + row + 8];
            #pragma unroll
            for (int nt = 0; nt < 8; nt++) {
                mma_bf16(acc[mt][nt], ah, bh[nt]);
                mma_bf16(acc[mt][nt], al, bh[nt]);
                mma_bf16(acc[mt][nt], ah, bl[nt]);
            }
        }

        if (more) sts(cur ^ 1);
        __syncthreads();
        cur ^= 1;
    }

    #pragma unroll
    for (int mt = 0; mt < 2; mt++) {
        #pragma unroll
        for (int nt = 0; nt < 8; nt++) {
            int row0 = bm + wm * 32 + mt * 16 + g;
            int col0 = bn + wn * 64 + nt * 8 + tig * 2;
            #pragma unroll
            for (int h = 0; h < 2; h++) {
                int row = row0 + h * 8;
                if (row < M) {
                    #pragma unroll
                    for (int w = 0; w < 2; w++) {
                        int col = col0 + w;
                        if (col < N) {
                            float v = acc[mt][nt][h * 2 + w];
                            // with split-K, only the z=0 slice adds the bias
                            if (BIASF && (SPLITK == 1 || blockIdx.z == 0)) v += bias[col];
                            if (SPLITK > 1) atomicAdd(&C[(size_t)row * N + col], v);
                            else            C[(size_t)row * N + col] = v;
                        }
                    }
                }
            }
        }
    }
}

// ---------------- row L2-normalize (warp per row) ----------------
__global__ void rownorm(const float* __restrict__ in, float* __restrict__ out, int R, int W) {
    int warp = threadIdx.x >> 5;
    int lane = threadIdx.x & 31;
    int row = blockIdx.x * 8 + warp;
    if (row >= R) return;
    const float* p = in + (size_t)row * W;
    float ss = 0.f;
    for (int cc = lane; cc < W; cc += 32) { float v = p[cc]; ss += v * v; }
    #pragma unroll
    for (int o = 16; o; o >>= 1) ss += __shfl_xor_sync(0xffffffffu, ss, o);
    float scale = 1.0f / fmaxf(sqrtf(ss), 1e-8f);
    float* q = out + (size_t)row * W;
    for (int cc = lane; cc < W; cc += 32) q[cc] = p[cc] * scale;
}

// ---------------- edge scatter-add: agg[dst] += m[src] ----------------
__global__ void scatter_add(const int* __restrict__ ei) {
    int i = blockIdx.x * blockDim.x + threadIdx.x;
    if (i >= NEDGE * (CC / 4)) return;
    int e  = i >> 8;
    int c4 = (i & 255) << 2;
    int src = ei[e];
    int dst = ei[NEDGE + e];
    float4 v = *(const float4*)&g_m[(size_t)src * CC + c4];
    float* a = &g_agg[(size_t)dst * CC + c4];
    atomicAdd(a + 0, v.x); atomicAdd(a + 1, v.y);
    atomicAdd(a + 2, v.z); atomicAdd(a + 3, v.w);
}

// ---------------- GRU cell update (in-place on g_hn) ----------------
__global__ void gru_gates(const float* __restrict__ bih, const float* __restrict__ bhh) {
    int i = blockIdx.x * blockDim.x + threadIdx.x;
    if (i >= BB * CC) return;
    int b = i >> 10;
    int j = i & 1023;
    size_t gb = (size_t)b * 3072;
    size_t gh = (size_t)BB * 3072 + gb;

    float ir  = g_gru[gb +        j] + bih[j];
    float iz  = g_gru[gb + 1024 + j] + bih[1024 + j];
    float in_ = g_gru[gb + 2048 + j] + bih[2048 + j];
    float hr  = g_gru[gh +        j] + bhh[j];
    float hz  = g_gru[gh + 1024 + j] + bhh[1024 + j];
    float hn  = g_gru[gh + 2048 + j] + bhh[2048 + j];

    float rg = sigf(ir + hr);
    float zg = sigf(iz + hz);
    float ng = tanhfast(in_ + rg * hn);
    float h = g_hn[i];
    g_hn[i] = (1.0f - zg) * ng + zg * h;
}

// ---------------- orchestration ----------------
extern "C" void kernel_launch(void* const* d_in, const int* in_sizes, int n_in,
                              void* d_out, int out_size)
{
    const int*   x        = (const int*)d_in[0];
    const int*   ei       = (const int*)d_in[1];
    const float* emb_tab  = (const float*)d_in[2];
    const float* Wih_f    = (const float*)d_in[3];
    const float* Whh_f    = (const float*)d_in[4];
    const float* bih_f    = (const float*)d_in[5];
    const float* bhh_f    = (const float*)d_in[6];
    const float* Wih_b    = (const float*)d_in[7];
    const float* Whh_b    = (const float*)d_in[8];
    const float* bih_b    = (const float*)d_in[9];
    const float* bhh_b    = (const float*)d_in[10];
    const float* label    = (const float*)d_in[11];
    const float* ggc_w    = (const float*)d_in[12];
    const float* gru_Wih  = (const float*)d_in[13];
    const float* gru_Whh  = (const float*)d_in[14];
    const float* gru_bih  = (const float*)d_in[15];
    const float* gru_bhh  = (const float*)d_in[16];
    const float* proj_W   = (const float*)d_in[17];
    const float* proj_b   = (const float*)d_in[18];
    float* out = (float*)d_out;

    float *p_gi, *p_c, *p_cs, *p_lnn, *p_hn, *p_m, *p_agg, *p_gru;
    float *p_hHf, *p_hLf;
    cudaGetSymbolAddress((void**)&p_gi,  g_gi);
    cudaGetSymbolAddress((void**)&p_c,   g_c);
    cudaGetSymbolAddress((void**)&p_cs,  g_cs);
    cudaGetSymbolAddress((void**)&p_lnn, g_lnn);
    cudaGetSymbolAddress((void**)&p_hn,  g_hn);
    cudaGetSymbolAddress((void**)&p_m,   g_m);
    cudaGetSymbolAddress((void**)&p_agg, g_agg);
    cudaGetSymbolAddress((void**)&p_gru, g_gru);
    cudaGetSymbolAddress((void**)&p_hHf, g_hH);
    cudaGetSymbolAddress((void**)&p_hLf, g_hL);

    const int TPB = 256;

    // 0) zero LSTM cell state + split-h buffers; pre-split Whh
    zerok<<<(2 * BB * HH + TPB - 1) / TPB, TPB>>>(p_cs, 2 * BB * HH);
    zerok<<<(2 * BB * KP + TPB - 1) / TPB, TPB>>>(p_hHf, 2 * BB * KP);
    zerok<<<(2 * BB * KP + TPB - 1) / TPB, TPB>>>(p_hLf, 2 * BB * KP);
    split_whh<<<(2 * G4 * KP + TPB - 1) / TPB, TPB>>>(Whh_f, Whh_b);

    // 1) input-to-hidden GEMMs with fused embedding gather (NT, GIDX)
    {
        dim3 grid((G4 + 127) / 128, (BT + 127) / 128, 2);
        gemm_bf<0, 0, 0, 1, 1><<<grid, 256>>>(emb_tab, Wih_f, p_gi,
                                              emb_tab, Wih_b, p_gi + (size_t)BT * G4,
                                              nullptr, x, BT, G4, EE);
    }

    // 2) recurrence: 64 steps, pre-split operands, 2 CTAs/SM
    for (int s = 0; s < TT; s++) {
        dim3 grid(10, 16, 2);
        gemm_rec<<<grid, 256>>>();
        lstm_gates<<<(2 * BB * KP + TPB - 1) / TPB, TPB>>>(bih_f, bhh_f, bih_b, bhh_b, s);
    }

    // 3) normalize c rows (in place) and label rows
    rownorm<<<(BT + 7) / 8, 256>>>(p_c, p_c, BT, D2);
    rownorm<<<(CC + 7) / 8, 256>>>(label, p_lnn, CC, D2);

    // 4) cosine similarity folded GEMM: [B, 38400] x periodic [1024, 600], split-K x8
    zerok<<<(BB * CC + TPB - 1) / TPB, TPB>>>(p_hn, BB * CC);
    {
        dim3 grid((CC + 127) / 128, (BB + 127) / 128, 8);
        gemm_bf<0, D2, 0, 8, 0><<<grid, 256>>>(p_c, p_lnn, p_hn,
                                               p_c, p_lnn, p_hn,
                                               nullptr, nullptr, BB, CC, KCOS);
    }

    // 5) GatedGraphConv, 2 layers
    for (int layer = 0; layer < 2; layer++) {
        // m = h @ W[layer]   (NN), split-K x2 to fill the chip
        zerok<<<(BB * CC + TPB - 1) / TPB, TPB>>>(p_m, BB * CC);
        {
            dim3 grid((CC + 127) / 128, (BB + 127) / 128, 2);
            gemm_bf<1, 0, 0, 2, 0><<<grid, 256>>>(p_hn, ggc_w + (size_t)layer * CC * CC, p_m,
                                                  p_hn, ggc_w + (size_t)layer * CC * CC, p_m,
                                                  nullptr, nullptr, BB, CC, CC);
        }
        zerok<<<(BB * CC + TPB - 1) / TPB, TPB>>>(p_agg, BB * CC);
        scatter_add<<<(NEDGE * (CC / 4) + TPB - 1) / TPB, TPB>>>(ei);
        {
            dim3 grid((3072 + 127) / 128, (BB + 127) / 128, 2);
            gemm_bf<0, 0, 0, 1, 0><<<grid, 256>>>(p_agg, gru_Wih, p_gru,
                                                  p_hn,  gru_Whh, p_gru + (size_t)BB * 3072,
                                                  nullptr, nullptr, BB, 3072, CC);
        }
        gru_gates<<<(BB * CC + TPB - 1) / TPB, TPB>>>(gru_bih, gru_bhh);
    }

    // 6) projection with bias -> d_out, split-K x2 (out pre-zeroed; bias on z==0 only)
    zerok<<<(BB * CC + TPB - 1) / TPB, TPB>>>(out, BB * CC);
    {
        dim3 grid((CC + 127) / 128, (BB + 127) / 128, 2);
        gemm_bf<0, 0, 1, 2, 0><<<grid, 256>>>(p_hn, proj_W, out,
                                              p_hn, proj_W, out,
                                              proj_b, nullptr, BB, CC, CC);
    }
}

// round 13
// speedup vs baseline: 1.6679x; 1.2574x over previous
#include <cuda_runtime.h>
#include <cuda_bf16.h>

// ---------------- problem constants ----------------
#define BB   2048          // batch / num nodes
#define TT   64            // seq len
#define EE   300           // embed dim = hidden
#define HH   300
#define G4   1200          // 4*H
#define D2   600           // 2*H
#define CC   1024          // num classes
#define NEDGE 65536
#define BT   (BB*TT)       // 131072
#define KP   152           // k-pairs for H=300 padded to 304

// ---------------- scratch (device globals; no cudaMalloc allowed) ----------------
__device__ float g_gi [(size_t)2 * BT * G4];
__device__ float g_c  [(size_t)BT * D2];
__device__ float g_S  [(size_t)BB * D2];            // t-summed normalized c
__device__ float g_cs [(size_t)2 * BB * HH];
__device__ float g_gg [(size_t)2 * BB * G4];
__device__ float g_lnn[(size_t)CC * D2];
__device__ float g_hn [(size_t)BB * CC];
__device__ float g_m  [(size_t)BB * CC];
__device__ float g_agg[(size_t)BB * CC];
__device__ float g_gru[(size_t)2 * BB * 3072];
// pre-split bf16x2 hi/lo: h state and Whh weights, layout [dir][row][kpair]
__device__ unsigned g_hH  [(size_t)2 * BB * KP];
__device__ unsigned g_hL  [(size_t)2 * BB * KP];
__device__ unsigned g_whhH[(size_t)2 * G4 * KP];
__device__ unsigned g_whhL[(size_t)2 * G4 * KP];

// ---------------- helpers ----------------
__device__ __forceinline__ float sigf(float x) { return 1.0f / (1.0f + __expf(-x)); }
__device__ __forceinline__ float tanhfast(float x) {
    return 2.0f / (1.0f + __expf(-2.0f * x)) - 1.0f;
}

__global__ void zerok(float* __restrict__ p, int n) {
    int i = blockIdx.x * blockDim.x + threadIdx.x;
    if (i < n) p[i] = 0.0f;
}

// ---------------- bf16 split helpers ----------------
__device__ __forceinline__ unsigned pack_hilo(float x, float y, unsigned& lo) {
    __nv_bfloat16 hx = __float2bfloat16_rn(x);
    __nv_bfloat16 hy = __float2bfloat16_rn(y);
    __nv_bfloat16 lx = __float2bfloat16_rn(x - __bfloat162float(hx));
    __nv_bfloat16 ly = __float2bfloat16_rn(y - __bfloat162float(hy));
    __nv_bfloat162 h2 = __halves2bfloat162(hx, hy);
    __nv_bfloat162 l2 = __halves2bfloat162(lx, ly);
    lo = *reinterpret_cast<unsigned*>(&l2);
    return *reinterpret_cast<unsigned*>(&h2);
}

__device__ __forceinline__ void mma_bf16(float* d, const unsigned* a, const unsigned* b) {
    asm volatile(
        "mma.sync.aligned.m16n8k16.row.col.f32.bf16.bf16.f32 "
        "{%0,%1,%2,%3},{%4,%5,%6,%7},{%8,%9},{%0,%1,%2,%3};\n"
        : "+f"(d[0]), "+f"(d[1]), "+f"(d[2]), "+f"(d[3])
        : "r"(a[0]), "r"(a[1]), "r"(a[2]), "r"(a[3]),
          "r"(b[0]), "r"(b[1]));
}

// ---------------- pre-split Whh into packed bf16x2 hi/lo ----------------
__global__ void split_whh(const float* __restrict__ Wf, const float* __restrict__ Wb) {
    int i = blockIdx.x * blockDim.x + threadIdx.x;
    if (i >= 2 * G4 * KP) return;
    int dir = i / (G4 * KP);
    int rem = i - dir * (G4 * KP);
    int n  = rem / KP;
    int kp = rem - n * KP;
    const float* W = dir ? Wb : Wf;
    int k = kp * 2;
    float x = (k     < HH) ? W[(size_t)n * HH + k]     : 0.f;
    float y = (k + 1 < HH) ? W[(size_t)n * HH + k + 1] : 0.f;
    unsigned lo, hi = pack_hilo(x, y, lo);
    g_whhH[i] = hi;
    g_whhL[i] = lo;
}

#define PADW 136

// ---------------- recurrence GEMM: gg[dir] = h[dir] @ Whh[dir]^T (pre-split) ----------------
// grid (10, 16, 2), block 256, 2 CTAs/SM
__global__ void __launch_bounds__(256, 2)
gemm_rec()
{
    __shared__ __align__(16) unsigned AsH[2][8 * PADW];
    __shared__ __align__(16) unsigned AsL[2][8 * PADW];
    __shared__ __align__(16) unsigned BsH[2][8 * PADW];
    __shared__ __align__(16) unsigned BsL[2][8 * PADW];

    const int t    = threadIdx.x;
    const int dir  = blockIdx.z;
    const int bm   = blockIdx.y * 128;
    const int bn   = blockIdx.x * 128;
    const int lr   = t & 127;
    const int half = t >> 7;           // 0/1 -> 4-kpair group within chunk
    const int wid  = t >> 5;
    const int wm   = wid >> 1;
    const int wn   = wid & 1;
    const int lane = t & 31;
    const int g    = lane >> 2;
    const int tig  = lane & 3;

    const unsigned* hHp = g_hH + ((size_t)(dir * BB + bm + lr)) * KP;
    const unsigned* hLp = g_hL + ((size_t)(dir * BB + bm + lr)) * KP;
    const int brow = bn + lr;
    const unsigned* wHp = (brow < G4) ? g_whhH + ((size_t)(dir * G4 + brow)) * KP : nullptr;
    const unsigned* wLp = (brow < G4) ? g_whhL + ((size_t)(dir * G4 + brow)) * KP : nullptr;

    float acc[2][8][4];
    #pragma unroll
    for (int i = 0; i < 2; i++)
        #pragma unroll
        for (int j = 0; j < 8; j++)
            #pragma unroll
            for (int q = 0; q < 4; q++) acc[i][j][q] = 0.0f;

    uint4 aH, aL, bH, bL;
    auto gload = [&](int chunk) {
        int kp0 = chunk * 8 + half * 4;
        aH = *(const uint4*)(hHp + kp0);
        aL = *(const uint4*)(hLp + kp0);
        if (wHp) {
            bH = *(const uint4*)(wHp + kp0);
            bL = *(const uint4*)(wLp + kp0);
        } else {
            bH = make_uint4(0u, 0u, 0u, 0u);
            bL = make_uint4(0u, 0u, 0u, 0u);
        }
    };
    auto sts = [&](int buf) {
        int p0 = half * 4;
        AsH[buf][(p0 + 0) * PADW + lr] = aH.x;
        AsH[buf][(p0 + 1) * PADW + lr] = aH.y;
        AsH[buf][(p0 + 2) * PADW + lr] = aH.z;
        AsH[buf][(p0 + 3) * PADW + lr] = aH.w;
        AsL[buf][(p0 + 0) * PADW + lr] = aL.x;
        AsL[buf][(p0 + 1) * PADW + lr] = aL.y;
        AsL[buf][(p0 + 2) * PADW + lr] = aL.z;
        AsL[buf][(p0 + 3) * PADW + lr] = aL.w;
        BsH[buf][(p0 + 0) * PADW + lr] = bH.x;
        BsH[buf][(p0 + 1) * PADW + lr] = bH.y;
        BsH[buf][(p0 + 2) * PADW + lr] = bH.z;
        BsH[buf][(p0 + 3) * PADW + lr] = bH.w;
        BsL[buf][(p0 + 0) * PADW + lr] = bL.x;
        BsL[buf][(p0 + 1) * PADW + lr] = bL.y;
        BsL[buf][(p0 + 2) * PADW + lr] = bL.z;
        BsL[buf][(p0 + 3) * PADW + lr] = bL.w;
    };

    gload(0);
    sts(0);
    __syncthreads();

    int cur = 0;
    for (int c = 0; c < 19; c++) {
        bool more = (c + 1) < 19;
        if (more) gload(c + 1);

        unsigned bh[8][2], bl[8][2];
        #pragma unroll
        for (int nt = 0; nt < 8; nt++) {
            int col = wn * 64 + nt * 8 + g;
            bh[nt][0] = BsH[cur][tig * PADW + col];
            bh[nt][1] = BsH[cur][(tig + 4) * PADW + col];
            bl[nt][0] = BsL[cur][tig * PADW + col];
            bl[nt][1] = BsL[cur][(tig + 4) * PADW + col];
        }
        #pragma unroll
        for (int mt = 0; mt < 2; mt++) {
            int row = wm * 32 + mt * 16 + g;
            unsigned ah[4], al[4];
            ah[0] = AsH[cur][tig * PADW + row];
            ah[1] = AsH[cur][tig * PADW + row + 8];
            ah[2] = AsH[cur][(tig + 4) * PADW + row];
            ah[3] = AsH[cur][(tig + 4) * PADW + row + 8];
            al[0] = AsL[cur][tig * PADW + row];
            al[1] = AsL[cur][tig * PADW + row + 8];
            al[2] = AsL[cur][(tig + 4) * PADW + row];
            al[3] = AsL[cur][(tig + 4) * PADW + row + 8];
            #pragma unroll
            for (int nt = 0; nt < 8; nt++) {
                mma_bf16(acc[mt][nt], ah, bh[nt]);  // hi*hi
                mma_bf16(acc[mt][nt], al, bh[nt]);  // lo*hi
                mma_bf16(acc[mt][nt], ah, bl[nt]);  // hi*lo
            }
        }

        if (more) sts(cur ^ 1);
        __syncthreads();
        cur ^= 1;
    }

    float* Cp = g_gg + (size_t)dir * BB * G4;
    #pragma unroll
    for (int mt = 0; mt < 2; mt++) {
        #pragma unroll
        for (int nt = 0; nt < 8; nt++) {
            int row0 = bm + wm * 32 + mt * 16 + g;
            int col0 = bn + wn * 64 + nt * 8 + tig * 2;
            #pragma unroll
            for (int h2 = 0; h2 < 2; h2++) {
                int row = row0 + h2 * 8;
                #pragma unroll
                for (int w = 0; w < 2; w++) {
                    int col = col0 + w;
                    if (col < G4)
                        Cp[(size_t)row * G4 + col] = acc[mt][nt][h2 * 2 + w];
                }
            }
        }
    }
}

// ---------------- LSTM gates: pointwise + write split h ----------------
__global__ void lstm_gates(const float* __restrict__ bih_f, const float* __restrict__ bhh_f,
                           const float* __restrict__ bih_b, const float* __restrict__ bhh_b,
                           int s)
{
    int p = blockIdx.x * blockDim.x + threadIdx.x;
    if (p >= 2 * BB * KP) return;
    int dir = p / (BB * KP);
    int rem = p - dir * (BB * KP);
    int b   = rem / KP;
    int kp  = rem - b * KP;
    int j0  = kp * 2;
    int tt  = dir ? (TT - 1 - s) : s;

    float h0 = 0.f, h1 = 0.f;
    if (j0 < HH) {
        const float* bi = dir ? bih_b : bih_f;
        const float* bh = dir ? bhh_b : bhh_f;
        size_t gg = (size_t)dir * BB * G4 + (size_t)b * G4;
        size_t gi = (size_t)dir * BT * G4 + ((size_t)b * TT + tt) * G4;
        #pragma unroll
        for (int u = 0; u < 2; u++) {
            int j = j0 + u;
            float xi = g_gg[gg +         j] + g_gi[gi +         j] + bi[j]        + bh[j];
            float xf = g_gg[gg +  HH   + j] + g_gi[gi +  HH   + j] + bi[HH + j]   + bh[HH + j];
            float xg = g_gg[gg + 2*HH  + j] + g_gi[gi + 2*HH  + j] + bi[2*HH + j] + bh[2*HH + j];
            float xo = g_gg[gg + 3*HH  + j] + g_gi[gi + 3*HH  + j] + bi[3*HH + j] + bh[3*HH + j];
            float ig = sigf(xi), fg = sigf(xf), cg = tanhfast(xg), og = sigf(xo);
            size_t ci = (size_t)dir * BB * HH + (size_t)b * HH + j;
            float cn = fg * g_cs[ci] + ig * cg;
            float hn = og * tanhfast(cn);
            g_cs[ci] = cn;
            g_c[((size_t)b * TT + tt) * D2 + dir * HH + j] = hn;
            if (u == 0) h0 = hn; else h1 = hn;
        }
    }
    unsigned lo, hi = pack_hilo(h0, h1, lo);
    g_hH[p] = hi;
    g_hL[p] = lo;
}

// ---------------- tensor-core GEMM (3xBF16, ~fp32-accurate) ----------------
template<int BLAY, int MODK, int BIASF, int SPLITK, int GIDX>
__global__ void __launch_bounds__(256, 2)
gemm_bf(const float* __restrict__ A0, const float* __restrict__ B0, float* __restrict__ C0,
        const float* __restrict__ A1, const float* __restrict__ B1, float* __restrict__ C1,
        const float* __restrict__ bias, const int* __restrict__ gidx,
        int M, int N, int K)
{
    __shared__ __align__(16) unsigned AsH[2][8 * PADW];
    __shared__ __align__(16) unsigned AsL[2][8 * PADW];
    __shared__ __align__(16) unsigned BsH[2][8 * PADW];
    __shared__ __align__(16) unsigned BsL[2][8 * PADW];

    const float* A; const float* Bm; float* C;
    int kbeg, kend;
    if (SPLITK > 1) {
        A = A0; Bm = B0; C = C0;
        int ks = K / SPLITK;
        kbeg = blockIdx.z * ks;
        kend = kbeg + ks;
    } else {
        A  = blockIdx.z ? A1 : A0;
        Bm = blockIdx.z ? B1 : B0;
        C  = blockIdx.z ? C1 : C0;
        kbeg = 0; kend = K;
    }

    const int t  = threadIdx.x;
    const int bm = blockIdx.y * 128;
    const int bn = blockIdx.x * 128;

    const int lr = t & 127;
    const int lk = (t >> 7) * 8;
    const int lp = t >> 5;
    const int lc = (t & 31) * 4;

    const int wid  = t >> 5;
    const int wm   = wid >> 1;
    const int wn   = wid & 1;
    const int lane = t & 31;
    const int g   = lane >> 2;
    const int tig = lane & 3;

    float acc[2][8][4];
    #pragma unroll
    for (int i = 0; i < 2; i++)
        #pragma unroll
        for (int j = 0; j < 8; j++)
            #pragma unroll
            for (int q = 0; q < 4; q++) acc[i][j][q] = 0.0f;

    float4 ra[2], rb[2];

    auto gload = [&](int k0) {
        {
            int row = bm + lr;
            const float* ap = nullptr;
            if (row < M) {
                long arow = GIDX ? (long)gidx[row] : (long)row;
                ap = A + (size_t)arow * K;
            }
            #pragma unroll
            for (int q = 0; q < 2; q++) {
                int k = k0 + lk + q * 4;
                float4 v = make_float4(0.f, 0.f, 0.f, 0.f);
                if (ap) {
                    if (k + 3 < kend) v = *(const float4*)(ap + k);
                    else {
                        if (k     < kend) v.x = ap[k];
                        if (k + 1 < kend) v.y = ap[k + 1];
                        if (k + 2 < kend) v.z = ap[k + 2];
                    }
                }
                ra[q] = v;
            }
        }
        if (BLAY == 0) {
            int row = bn + lr;
            #pragma unroll
            for (int q = 0; q < 2; q++) {
                int k = k0 + lk + q * 4;
                float4 v = make_float4(0.f, 0.f, 0.f, 0.f);
                if (row < N) {
                    if (MODK > 0) {
                        v = *(const float4*)(Bm + (size_t)row * MODK + (k % MODK));
                    } else {
                        const float* bp = Bm + (size_t)row * K;
                        if (k + 3 < kend) v = *(const float4*)(bp + k);
                        else {
                            if (k     < kend) v.x = bp[k];
                            if (k + 1 < kend) v.y = bp[k + 1];
                            if (k + 2 < kend) v.z = bp[k + 2];
                        }
                    }
                }
                rb[q] = v;
            }
        } else {
            #pragma unroll
            for (int q = 0; q < 2; q++) {
                int k = k0 + 2 * lp + q;
                float4 v = make_float4(0.f, 0.f, 0.f, 0.f);
                if (k < kend) {
                    const float* bp = Bm + (size_t)k * N;
                    int col = bn + lc;
                    if (col + 3 < N) v = *(const float4*)(bp + col);
                    else {
                        if (col     < N) v.x = bp[col];
                        if (col + 1 < N) v.y = bp[col + 1];
                        if (col + 2 < N) v.z = bp[col + 2];
                    }
                }
                rb[q] = v;
            }
        }
    };

    auto sts = [&](int buf) {
        #pragma unroll
        for (int q = 0; q < 2; q++) {
            int p = (lk >> 1) + 2 * q;
            unsigned lo0, lo1;
            unsigned h0 = pack_hilo(ra[q].x, ra[q].y, lo0);
            unsigned h1 = pack_hilo(ra[q].z, ra[q].w, lo1);
            AsH[buf][p * PADW + lr]       = h0;
            AsL[buf][p * PADW + lr]       = lo0;
            AsH[buf][(p + 1) * PADW + lr] = h1;
            AsL[buf][(p + 1) * PADW + lr] = lo1;
        }
        if (BLAY == 0) {
            #pragma unroll
            for (int q = 0; q < 2; q++) {
                int p = (lk >> 1) + 2 * q;
                unsigned lo0, lo1;
                unsigned h0 = pack_hilo(rb[q].x, rb[q].y, lo0);
                unsigned h1 = pack_hilo(rb[q].z, rb[q].w, lo1);
                BsH[buf][p * PADW + lr]       = h0;
                BsL[buf][p * PADW + lr]       = lo0;
                BsH[buf][(p + 1) * PADW + lr] = h1;
                BsL[buf][(p + 1) * PADW + lr] = lo1;
            }
        } else {
            uint4 h4, l4;
            h4.x = pack_hilo(rb[0].x, rb[1].x, l4.x);
            h4.y = pack_hilo(rb[0].y, rb[1].y, l4.y);
            h4.z = pack_hilo(rb[0].z, rb[1].z, l4.z);
            h4.w = pack_hilo(rb[0].w, rb[1].w, l4.w);
            *(uint4*)&BsH[buf][lp * PADW + lc] = h4;
            *(uint4*)&BsL[buf][lp * PADW + lc] = l4;
        }
    };

    gload(kbeg);
    sts(0);
    __syncthreads();

    int cur = 0;
    for (int k0 = kbeg; k0 < kend; k0 += 16) {
        bool more = (k0 + 16) < kend;
        if (more) gload(k0 + 16);

        unsigned bh[8][2], bl[8][2];
        #pragma unroll
        for (int nt = 0; nt < 8; nt++) {
            int col = wn * 64 + nt * 8 + g;
            bh[nt][0] = BsH[cur][tig * PADW + col];
            bh[nt][1] = BsH[cur][(tig + 4) * PADW + col];
            bl[nt][0] = BsL[cur][tig * PADW + col];
            bl[nt][1] = BsL[cur][(tig + 4) * PADW + col];
        }
        #pragma unroll
        for (int mt = 0; mt < 2; mt++) {
            int row = wm * 32 + mt * 16 + g;
            unsigned ah[4], al[4];
            ah[0] = AsH[cur][tig * PADW + row];
            ah[1] = AsH[cur][tig * PADW + row + 8];
            ah[2] = AsH[cur][(tig + 4) * PADW + row];
            ah[3] = AsH[cur][(tig + 4) * PADW + row + 8];
            al[0] = AsL[cur][tig * PADW + row];
            al[1] = AsL[cur][tig * PADW + row + 8];
            al[2] = AsL[cur][(tig + 4) * PADW + row];
            al[3] = AsL[cur][(tig + 4) * PADW + row + 8];
            #pragma unroll
            for (int nt = 0; nt < 8; nt++) {
                mma_bf16(acc[mt][nt], ah, bh[nt]);
                mma_bf16(acc[mt][nt], al, bh[nt]);
                mma_bf16(acc[mt][nt], ah, bl[nt]);
            }
        }

        if (more) sts(cur ^ 1);
        __syncthreads();
        cur ^= 1;
    }

    #pragma unroll
    for (int mt = 0; mt < 2; mt++) {
        #pragma unroll
        for (int nt = 0; nt < 8; nt++) {
            int row0 = bm + wm * 32 + mt * 16 + g;
            int col0 = bn + wn * 64 + nt * 8 + tig * 2;
            #pragma unroll
            for (int h = 0; h < 2; h++) {
                int row = row0 + h * 8;
                if (row < M) {
                    #pragma unroll
                    for (int w = 0; w < 2; w++) {
                        int col = col0 + w;
                        if (col < N) {
                            float v = acc[mt][nt][h * 2 + w];
                            // with split-K, only the z=0 slice adds the bias
                            if (BIASF && (SPLITK == 1 || blockIdx.z == 0)) v += bias[col];
                            if (SPLITK > 1) atomicAdd(&C[(size_t)row * N + col], v);
                            else            C[(size_t)row * N + col] = v;
                        }
                    }
                }
            }
        }
    }
}

// ---------------- fused row-normalize + t-sum: S[b,:] = sum_t c[b,t,:]/||c[b,t,:]|| ----------------
// block per b (2048 blocks), 8 warps; each warp handles t = warp, warp+8, ...
__global__ void normsum(const float* __restrict__ c, float* __restrict__ S) {
    __shared__ float Ss[D2];
    int b    = blockIdx.x;
    int tid  = threadIdx.x;
    int warp = tid >> 5;
    int lane = tid & 31;
    for (int i = tid; i < D2; i += 256) Ss[i] = 0.0f;
    __syncthreads();
    for (int t = warp; t < TT; t += 8) {
        const float* p = c + ((size_t)b * TT + t) * D2;
        float ss = 0.f;
        for (int cc = lane; cc < D2; cc += 32) { float v = p[cc]; ss += v * v; }
        #pragma unroll
        for (int o = 16; o; o >>= 1) ss += __shfl_xor_sync(0xffffffffu, ss, o);
        float scale = 1.0f / fmaxf(sqrtf(ss), 1e-8f);
        for (int cc = lane; cc < D2; cc += 32) atomicAdd(&Ss[cc], p[cc] * scale);
    }
    __syncthreads();
    for (int i = tid; i < D2; i += 256) S[(size_t)b * D2 + i] = Ss[i];
}

// ---------------- row L2-normalize (warp per row) ----------------
__global__ void rownorm(const float* __restrict__ in, float* __restrict__ out, int R, int W) {
    int warp = threadIdx.x >> 5;
    int lane = threadIdx.x & 31;
    int row = blockIdx.x * 8 + warp;
    if (row >= R) return;
    const float* p = in + (size_t)row * W;
    float ss = 0.f;
    for (int cc = lane; cc < W; cc += 32) { float v = p[cc]; ss += v * v; }
    #pragma unroll
    for (int o = 16; o; o >>= 1) ss += __shfl_xor_sync(0xffffffffu, ss, o);
    float scale = 1.0f / fmaxf(sqrtf(ss), 1e-8f);
    float* q = out + (size_t)row * W;
    for (int cc = lane; cc < W; cc += 32) q[cc] = p[cc] * scale;
}

// ---------------- edge scatter-add: agg[dst] += m[src] ----------------
__global__ void scatter_add(const int* __restrict__ ei) {
    int i = blockIdx.x * blockDim.x + threadIdx.x;
    if (i >= NEDGE * (CC / 4)) return;
    int e  = i >> 8;
    int c4 = (i & 255) << 2;
    int src = ei[e];
    int dst = ei[NEDGE + e];
    float4 v = *(const float4*)&g_m[(size_t)src * CC + c4];
    float* a = &g_agg[(size_t)dst * CC + c4];
    atomicAdd(a + 0, v.x); atomicAdd(a + 1, v.y);
    atomicAdd(a + 2, v.z); atomicAdd(a + 3, v.w);
}

// ---------------- GRU cell update (in-place on g_hn) ----------------
__global__ void gru_gates(const float* __restrict__ bih, const float* __restrict__ bhh) {
    int i = blockIdx.x * blockDim.x + threadIdx.x;
    if (i >= BB * CC) return;
    int b = i >> 10;
    int j = i & 1023;
    size_t gb = (size_t)b * 3072;
    size_t gh = (size_t)BB * 3072 + gb;

    float ir  = g_gru[gb +        j] + bih[j];
    float iz  = g_gru[gb + 1024 + j] + bih[1024 + j];
    float in_ = g_gru[gb + 2048 + j] + bih[2048 + j];
    float hr  = g_gru[gh +        j] + bhh[j];
    float hz  = g_gru[gh + 1024 + j] + bhh[1024 + j];
    float hn  = g_gru[gh + 2048 + j] + bhh[2048 + j];

    float rg = sigf(ir + hr);
    float zg = sigf(iz + hz);
    float ng = tanhfast(in_ + rg * hn);
    float h = g_hn[i];
    g_hn[i] = (1.0f - zg) * ng + zg * h;
}

// ---------------- orchestration ----------------
extern "C" void kernel_launch(void* const* d_in, const int* in_sizes, int n_in,
                              void* d_out, int out_size)
{
    const int*   x        = (const int*)d_in[0];
    const int*   ei       = (const int*)d_in[1];
    const float* emb_tab  = (const float*)d_in[2];
    const float* Wih_f    = (const float*)d_in[3];
    const float* Whh_f    = (const float*)d_in[4];
    const float* bih_f    = (const float*)d_in[5];
    const float* bhh_f    = (const float*)d_in[6];
    const float* Wih_b    = (const float*)d_in[7];
    const float* Whh_b    = (const float*)d_in[8];
    const float* bih_b    = (const float*)d_in[9];
    const float* bhh_b    = (const float*)d_in[10];
    const float* label    = (const float*)d_in[11];
    const float* ggc_w    = (const float*)d_in[12];
    const float* gru_Wih  = (const float*)d_in[13];
    const float* gru_Whh  = (const float*)d_in[14];
    const float* gru_bih  = (const float*)d_in[15];
    const float* gru_bhh  = (const float*)d_in[16];
    const float* proj_W   = (const float*)d_in[17];
    const float* proj_b   = (const float*)d_in[18];
    float* out = (float*)d_out;

    float *p_gi, *p_c, *p_S, *p_cs, *p_lnn, *p_hn, *p_m, *p_agg, *p_gru;
    float *p_hHf, *p_hLf;
    cudaGetSymbolAddress((void**)&p_gi,  g_gi);
    cudaGetSymbolAddress((void**)&p_c,   g_c);
    cudaGetSymbolAddress((void**)&p_S,   g_S);
    cudaGetSymbolAddress((void**)&p_cs,  g_cs);
    cudaGetSymbolAddress((void**)&p_lnn, g_lnn);
    cudaGetSymbolAddress((void**)&p_hn,  g_hn);
    cudaGetSymbolAddress((void**)&p_m,   g_m);
    cudaGetSymbolAddress((void**)&p_agg, g_agg);
    cudaGetSymbolAddress((void**)&p_gru, g_gru);
    cudaGetSymbolAddress((void**)&p_hHf, g_hH);
    cudaGetSymbolAddress((void**)&p_hLf, g_hL);

    const int TPB = 256;

    // 0) zero LSTM cell state + split-h buffers; pre-split Whh
    zerok<<<(2 * BB * HH + TPB - 1) / TPB, TPB>>>(p_cs, 2 * BB * HH);
    zerok<<<(2 * BB * KP + TPB - 1) / TPB, TPB>>>(p_hHf, 2 * BB * KP);
    zerok<<<(2 * BB * KP + TPB - 1) / TPB, TPB>>>(p_hLf, 2 * BB * KP);
    split_whh<<<(2 * G4 * KP + TPB - 1) / TPB, TPB>>>(Whh_f, Whh_b);

    // 1) input-to-hidden GEMMs with fused embedding gather (NT, GIDX)
    {
        dim3 grid((G4 + 127) / 128, (BT + 127) / 128, 2);
        gemm_bf<0, 0, 0, 1, 1><<<grid, 256>>>(emb_tab, Wih_f, p_gi,
                                              emb_tab, Wih_b, p_gi + (size_t)BT * G4,
                                              nullptr, x, BT, G4, EE);
    }

    // 2) recurrence: 64 steps, pre-split operands, 2 CTAs/SM
    for (int s = 0; s < TT; s++) {
        dim3 grid(10, 16, 2);
        gemm_rec<<<grid, 256>>>();
        lstm_gates<<<(2 * BB * KP + TPB - 1) / TPB, TPB>>>(bih_f, bhh_f, bih_b, bhh_b, s);
    }

    // 3) fused normalize + t-sum of c -> S[B,600]; normalize label rows
    normsum<<<BB, 256>>>(p_c, p_S);
    rownorm<<<(CC + 7) / 8, 256>>>(label, p_lnn, CC, D2);

    // 4) cosine similarity (t-sum factored out): [2048,600] x [1024,600]^T, split-K x2
    zerok<<<(BB * CC + TPB - 1) / TPB, TPB>>>(p_hn, BB * CC);
    {
        dim3 grid((CC + 127) / 128, (BB + 127) / 128, 2);
        gemm_bf<0, 0, 0, 2, 0><<<grid, 256>>>(p_S, p_lnn, p_hn,
                                              p_S, p_lnn, p_hn,
                                              nullptr, nullptr, BB, CC, D2);
    }

    // 5) GatedGraphConv, 2 layers
    for (int layer = 0; layer < 2; layer++) {
        // m = h @ W[layer]   (NN), split-K x2 to fill the chip
        zerok<<<(BB * CC + TPB - 1) / TPB, TPB>>>(p_m, BB * CC);
        {
            dim3 grid((CC + 127) / 128, (BB + 127) / 128, 2);
            gemm_bf<1, 0, 0, 2, 0><<<grid, 256>>>(p_hn, ggc_w + (size_t)layer * CC * CC, p_m,
                                                  p_hn, ggc_w + (size_t)layer * CC * CC, p_m,
                                                  nullptr, nullptr, BB, CC, CC);
        }
        zerok<<<(BB * CC + TPB - 1) / TPB, TPB>>>(p_agg, BB * CC);
        scatter_add<<<(NEDGE * (CC / 4) + TPB - 1) / TPB, TPB>>>(ei);
        {
            dim3 grid((3072 + 127) / 128, (BB + 127) / 128, 2);
            gemm_bf<0, 0, 0, 1, 0><<<grid, 256>>>(p_agg, gru_Wih, p_gru,
                                                  p_hn,  gru_Whh, p_gru + (size_t)BB * 3072,
                                                  nullptr, nullptr, BB, 3072, CC);
        }
        gru_gates<<<(BB * CC + TPB - 1) / TPB, TPB>>>(gru_bih, gru_bhh);
    }

    // 6) projection with bias -> d_out, split-K x2 (out pre-zeroed; bias on z==0 only)
    zerok<<<(BB * CC + TPB - 1) / TPB, TPB>>>(out, BB * CC);
    {
        dim3 grid((CC + 127) / 128, (BB + 127) / 128, 2);
        gemm_bf<0, 0, 1, 2, 0><<<grid, 256>>>(p_hn, proj_W, out,
                                              p_hn, proj_W, out,
                                              proj_b, nullptr, BB, CC, CC);
    }
}